// round 1
// baseline (speedup 1.0000x reference)
#include <cuda_runtime.h>
#include <math.h>

#define BB 32
#define TT 1024
#define DD 512
#define HH 512

// ---------------- scratch (device globals: allocation-free) ----------------
__device__ float g_pre[TT * BB * HH];   // 64 MB: per-layer input transform, [t][b][j]
__device__ float g_y0 [TT * BB * HH];   // 64 MB: layer-0 outputs, [t][b][j]
__device__ float g_h  [2][BB * HH];     // recurrent state double buffer
__device__ unsigned g_barCnt;           // zero-initialized
__device__ unsigned g_barGen;

// ---------------- grid barrier (sense-reversing, all CTAs resident) --------
__device__ __forceinline__ void grid_barrier(int nblk) {
    __threadfence();            // release: make this thread's STGs visible
    __syncthreads();            // all threads in CTA fenced before arrival
    if (threadIdx.x == 0) {
        volatile unsigned* vgen = &g_barGen;
        unsigned g = *vgen;
        if (atomicAdd(&g_barCnt, 1u) == (unsigned)(nblk - 1)) {
            g_barCnt = 0;
            __threadfence();
            *vgen = g + 1;
        } else {
            while (*vgen == g) { }
        }
        __threadfence();        // acquire
    }
    __syncthreads();
}

// ---------------- pre-GEMM: pre[t*B+b][j] = A_row . W[j] + (b1[j]+b2[j]) ---
// mode 0: A = x [B][T][D], row m=(t*B+b) -> x + (b*T+t)*D
// mode 1: A = g_y0 [T*B][D], row m -> g_y0 + m*D
__global__ __launch_bounds__(256) void gemm_pre(
    const float* __restrict__ A, const float* __restrict__ W,
    const float* __restrict__ b1, const float* __restrict__ b2, int mode)
{
    __shared__ float As[16][68];
    __shared__ float Bs[16][68];

    const int m0 = blockIdx.y * 64;
    const int n0 = blockIdx.x * 64;
    const int tid = threadIdx.x;
    const int r  = tid >> 2;     // 0..63 (row within tile for loads)
    const int kq = tid & 3;      // 0..3  (k-quad within 16-wide k-tile)
    const int tx = tid & 15;     // micro-tile n
    const int ty = tid >> 4;     // micro-tile m

    const float* Abase = (mode == 0) ? A : g_y0;
    const int m = m0 + r;
    const float* arow;
    if (mode == 0) {
        int t = m >> 5, b = m & 31;
        arow = Abase + ((size_t)b * TT + t) * DD;
    } else {
        arow = Abase + (size_t)m * DD;
    }
    const float* brow = W + (size_t)(n0 + r) * DD;

    float acc[4][4];
#pragma unroll
    for (int i = 0; i < 4; i++)
#pragma unroll
        for (int j = 0; j < 4; j++) acc[i][j] = 0.f;

    float4 a_next = *(const float4*)(arow + kq * 4);
    float4 b_next = *(const float4*)(brow + kq * 4);

    for (int kt = 0; kt < DD / 16; kt++) {
        float4 a = a_next, bv = b_next;
        As[kq*4+0][r] = a.x;  As[kq*4+1][r] = a.y;
        As[kq*4+2][r] = a.z;  As[kq*4+3][r] = a.w;
        Bs[kq*4+0][r] = bv.x; Bs[kq*4+1][r] = bv.y;
        Bs[kq*4+2][r] = bv.z; Bs[kq*4+3][r] = bv.w;
        __syncthreads();
        if (kt + 1 < DD / 16) {
            a_next = *(const float4*)(arow + (kt + 1) * 16 + kq * 4);
            b_next = *(const float4*)(brow + (kt + 1) * 16 + kq * 4);
        }
#pragma unroll
        for (int k = 0; k < 16; k++) {
            float4 av = *(const float4*)&As[k][ty * 4];
            float4 bw = *(const float4*)&Bs[k][tx * 4];
            float am[4] = {av.x, av.y, av.z, av.w};
            float bn[4] = {bw.x, bw.y, bw.z, bw.w};
#pragma unroll
            for (int i = 0; i < 4; i++)
#pragma unroll
                for (int j = 0; j < 4; j++) acc[i][j] += am[i] * bn[j];
        }
        __syncthreads();
    }

    float bias[4];
#pragma unroll
    for (int j = 0; j < 4; j++) {
        int n = n0 + tx * 4 + j;
        bias[j] = b1[n] + b2[n];
    }
#pragma unroll
    for (int i = 0; i < 4; i++) {
        int mo = m0 + ty * 4 + i;
        float4 v;
        v.x = acc[i][0] + bias[0];
        v.y = acc[i][1] + bias[1];
        v.z = acc[i][2] + bias[2];
        v.w = acc[i][3] + bias[3];
        *(float4*)&g_pre[(size_t)mo * HH + n0 + tx * 4] = v;
    }
}

// ---------------- persistent recurrence ------------------------------------
// 128 CTAs = 4 batch-groups (8 batches) x 32 j-groups (16 rows). 128 thr/CTA.
// SMEM: Ws[16][516] (W_hh slice, cached all steps) + Hs[8][516] (h tile).
#define WPITCH 516
#define REC_SMEM ((16 * WPITCH + 8 * WPITCH) * 4)

__global__ __launch_bounds__(128) void rnn_recur(
    const float* __restrict__ Whh, int layer, float* __restrict__ out)
{
    extern __shared__ float smem[];
    float* Ws = smem;                // 16 x 516
    float* Hs = smem + 16 * WPITCH;  // 8 x 516

    const int bg = blockIdx.x >> 5;   // 0..3
    const int jg = blockIdx.x & 31;   // 0..31
    const int tid = threadIdx.x;
    const int jl = tid & 15;
    const int bl = tid >> 4;          // 0..7
    const int b = bg * 8 + bl;
    const int j = jg * 16 + jl;

    // cache W_hh rows [jg*16, jg*16+16) in SMEM once
    for (int i = tid; i < 16 * 128; i += 128) {
        int row = i >> 7, kq4 = i & 127;
        float4 w = *(const float4*)(Whh + (size_t)(jg * 16 + row) * HH + kq4 * 4);
        *(float4*)&Ws[row * WPITCH + kq4 * 4] = w;
    }
    __syncthreads();

    const float* wr = Ws + jl * WPITCH;
    const float* hr = Hs + bl * WPITCH;
    float* hiddenOut = out + (size_t)BB * TT * HH + (size_t)layer * BB * HH;

    for (int t = 0; t < TT; t++) {
        // prefetch this step's input-transform value early (DRAM stream)
        float pv = g_pre[((size_t)t * BB + b) * HH + j];

        float accv = 0.f;
        if (t > 0) {
            const float* hsrc = g_h[(t + 1) & 1];  // h from step t-1
            // stage h rows [bg*8, bg*8+8) into SMEM
#pragma unroll
            for (int q = 0; q < 8; q++) {
                int idx = q * 128 + tid;       // one full 512-float row per q
                int row = idx >> 7, kq4 = idx & 127;
                float4 v = *(const float4*)(hsrc + (size_t)(bg * 8 + row) * HH + kq4 * 4);
                *(float4*)&Hs[row * WPITCH + kq4 * 4] = v;
            }
            __syncthreads();

            float a0 = 0.f, a1 = 0.f, a2 = 0.f, a3 = 0.f;
#pragma unroll 8
            for (int kq4 = 0; kq4 < 128; kq4++) {
                float4 w  = *(const float4*)(wr + kq4 * 4);
                float4 h4 = *(const float4*)(hr + kq4 * 4);
                a0 += w.x * h4.x;
                a1 += w.y * h4.y;
                a2 += w.z * h4.z;
                a3 += w.w * h4.w;
            }
            accv = (a0 + a1) + (a2 + a3);
        }

        float hn = tanhf(pv + accv);

        if (layer == 0) {
            g_y0[((size_t)t * BB + b) * HH + j] = hn;           // [t][b][j]
        } else {
            out[((size_t)b * TT + t) * HH + j] = hn;            // y1 [b][t][j]
        }
        g_h[t & 1][b * HH + j] = hn;
        if (t == TT - 1) hiddenOut[b * HH + j] = hn;

        grid_barrier(gridDim.x);
    }
}

// ---------------- launch ----------------------------------------------------
extern "C" void kernel_launch(void* const* d_in, const int* in_sizes, int n_in,
                              void* d_out, int out_size)
{
    (void)in_sizes; (void)n_in; (void)out_size;
    const float* x    = (const float*)d_in[0];
    const float* wih0 = (const float*)d_in[1];
    const float* whh0 = (const float*)d_in[2];
    const float* bih0 = (const float*)d_in[3];
    const float* bhh0 = (const float*)d_in[4];
    const float* wih1 = (const float*)d_in[5];
    const float* whh1 = (const float*)d_in[6];
    const float* bih1 = (const float*)d_in[7];
    const float* bhh1 = (const float*)d_in[8];
    float* out = (float*)d_out;

    cudaFuncSetAttribute(rnn_recur,
                         cudaFuncAttributeMaxDynamicSharedMemorySize, REC_SMEM);

    dim3 gemmGrid(HH / 64, (TT * BB) / 64);   // (8, 512)

    // layer 0
    gemm_pre<<<gemmGrid, 256>>>(x, wih0, bih0, bhh0, 0);
    rnn_recur<<<128, 128, REC_SMEM>>>(whh0, 0, out);
    // layer 1
    gemm_pre<<<gemmGrid, 256>>>(nullptr, wih1, bih1, bhh1, 1);
    rnn_recur<<<128, 128, REC_SMEM>>>(whh1, 1, out);
}

// round 3
// speedup vs baseline: 2.2636x; 2.2636x over previous
#include <cuda_runtime.h>
#include <math.h>

#define BB 32
#define TT 1024
#define DD 512
#define HH 512

// ---------------- scratch (device globals: allocation-free) ----------------
__device__ float g_pre[TT * BB * HH];     // 64 MB: layer-0 input transform + bias, [t][b][j]
__device__ float g_h0[2][BB][HH];         // layer-0 hidden double buffer
__device__ float g_h1[2][BB][HH];         // layer-1 hidden double buffer
__device__ unsigned g_cnt[4 * 128];       // per-batch-group barrier counters (512B apart)
__device__ unsigned g_gen[4 * 128];       // per-batch-group generations

// ---------------- atomics helpers ------------------------------------------
__device__ __forceinline__ unsigned ldacq(const unsigned* p) {
    unsigned v;
    asm volatile("ld.acquire.gpu.u32 %0, [%1];" : "=r"(v) : "l"(p) : "memory");
    return v;
}
__device__ __forceinline__ void strel(unsigned* p, unsigned v) {
    asm volatile("st.release.gpu.u32 [%0], %1;" :: "l"(p), "r"(v) : "memory");
}
__device__ __forceinline__ void fma2(unsigned long long& d,
                                     unsigned long long a, unsigned long long b) {
    asm("fma.rn.f32x2 %0, %1, %2, %0;" : "+l"(d) : "l"(a), "l"(b));
}

// ---------------- init: zero recurrent state + barriers ---------------------
__global__ void init_state() {
    int idx = blockIdx.x * blockDim.x + threadIdx.x;
    if (idx < 2 * BB * HH) {
        ((float*)g_h0)[idx] = 0.f;
        ((float*)g_h1)[idx] = 0.f;
    }
    if (idx < 4) { g_cnt[idx * 128] = 0; g_gen[idx * 128] = 0; }
}

// ---------------- pre-GEMM (layer 0 only): pre[t*B+b][j] = x_row.W[j]+bias --
__global__ __launch_bounds__(256) void gemm_pre(
    const float* __restrict__ X, const float* __restrict__ W,
    const float* __restrict__ b1, const float* __restrict__ b2)
{
    __shared__ float As[16][68];
    __shared__ float Bs[16][68];

    const int m0 = blockIdx.y * 64;
    const int n0 = blockIdx.x * 64;
    const int tid = threadIdx.x;
    const int r  = tid >> 2;
    const int kq = tid & 3;
    const int tx = tid & 15;
    const int ty = tid >> 4;

    const int m = m0 + r;
    const int t = m >> 5, b = m & 31;
    const float* arow = X + ((size_t)b * TT + t) * DD;
    const float* brow = W + (size_t)(n0 + r) * DD;

    float acc[4][4];
#pragma unroll
    for (int i = 0; i < 4; i++)
#pragma unroll
        for (int j = 0; j < 4; j++) acc[i][j] = 0.f;

    float4 a_next = *(const float4*)(arow + kq * 4);
    float4 b_next = *(const float4*)(brow + kq * 4);

    for (int kt = 0; kt < DD / 16; kt++) {
        float4 a = a_next, bv = b_next;
        As[kq*4+0][r] = a.x;  As[kq*4+1][r] = a.y;
        As[kq*4+2][r] = a.z;  As[kq*4+3][r] = a.w;
        Bs[kq*4+0][r] = bv.x; Bs[kq*4+1][r] = bv.y;
        Bs[kq*4+2][r] = bv.z; Bs[kq*4+3][r] = bv.w;
        __syncthreads();
        if (kt + 1 < DD / 16) {
            a_next = *(const float4*)(arow + (kt + 1) * 16 + kq * 4);
            b_next = *(const float4*)(brow + (kt + 1) * 16 + kq * 4);
        }
#pragma unroll
        for (int k = 0; k < 16; k++) {
            float4 av = *(const float4*)&As[k][ty * 4];
            float4 bw = *(const float4*)&Bs[k][tx * 4];
            float am[4] = {av.x, av.y, av.z, av.w};
            float bn[4] = {bw.x, bw.y, bw.z, bw.w};
#pragma unroll
            for (int i = 0; i < 4; i++)
#pragma unroll
                for (int j = 0; j < 4; j++) acc[i][j] += am[i] * bn[j];
        }
        __syncthreads();
    }

    float bias[4];
#pragma unroll
    for (int j = 0; j < 4; j++) {
        int n = n0 + tx * 4 + j;
        bias[j] = b1[n] + b2[n];
    }
#pragma unroll
    for (int i = 0; i < 4; i++) {
        int mo = m0 + ty * 4 + i;
        float4 v;
        v.x = acc[i][0] + bias[0];
        v.y = acc[i][1] + bias[1];
        v.z = acc[i][2] + bias[2];
        v.w = acc[i][3] + bias[3];
        *(float4*)&g_pre[(size_t)mo * HH + n0 + tx * 4] = v;
    }
}

// ---------------- fused 2-layer persistent recurrence -----------------------
// 128 CTAs = 32 j-groups (16 rows) x 4 batch-groups (8 batches). 384 threads.
// Round r (r=0..TT):
//   if r <  TT: h0[r]   = tanh(pre[r]       + Whh0 @ h0[r-1])          (mat 0)
//   if r >= 1 : h1[r-1] = tanh(b1 + Wih1 @ h0[r-1] + Whh1 @ h1[r-2])   (mats 1,2)
// Per-batch-group barrier (32 arrivals) between rounds.
#define WP 520
#define HP 516
#define RP 9
#define SMEM_FUSED ((48*WP + 2*8*HP + 48*8*RP + 16) * 4)

__global__ __launch_bounds__(384, 1) void rnn_fused(
    const float* __restrict__ Whh0, const float* __restrict__ Wih1,
    const float* __restrict__ Whh1, const float* __restrict__ bih1,
    const float* __restrict__ bhh1, float* __restrict__ out)
{
    extern __shared__ float sm[];
    float* Ws  = sm;                     // 48 x WP  (rows: 16 Whh0, 16 Wih1, 16 Whh1)
    float* Hs0 = Ws  + 48 * WP;          // 8 x HP
    float* Hs1 = Hs0 + 8 * HP;           // 8 x HP
    float* red = Hs1 + 8 * HP;           // 48*8*RP partials
    float* b1s = red + 48 * 8 * RP;      // 16 biases

    const int tid  = threadIdx.x;
    const int wid  = tid >> 5;
    const int lane = tid & 31;
    const int bg = blockIdx.x >> 5;      // 0..3
    const int jg = blockIdx.x & 31;      // 0..31

    const int mat = wid % 3;             // SMSP = wid%4 -> each SMSP gets mats {0,1,2}
    const int wom = wid / 3;             // 0..3
    const int jq   = lane & 3;
    const int bq   = (lane >> 2) & 3;
    const int kshi = lane >> 4;
    const int ks   = wom * 2 + kshi;     // 0..7 (k-slice)

    // ---- load stacked weight slice into smem (once) ----
    for (int i = tid; i < 48 * 128; i += 384) {
        int row = i >> 7, kq = i & 127;
        const float* src = (row < 16) ? Whh0 + (size_t)(jg * 16 + row) * HH
                         : (row < 32) ? Wih1 + (size_t)(jg * 16 + row - 16) * HH
                                      : Whh1 + (size_t)(jg * 16 + row - 32) * HH;
        *(float4*)&Ws[row * WP + kq * 4] = *(const float4*)(src + kq * 4);
    }
    if (tid < 16) b1s[tid] = bih1[jg * 16 + tid] + bhh1[jg * 16 + tid];

    unsigned* cnt = &g_cnt[bg * 128];
    unsigned* gen = &g_gen[bg * 128];

    const int ej = tid & 15;             // epilogue j (within slice)
    const int eb = (tid >> 4) & 7;       // epilogue b (within group)
    const int gb = bg * 8 + eb;          // global batch
    const int gj = jg * 16 + ej;         // global j

    float pv = 0.f;
    if (tid < 128) pv = g_pre[((size_t)0 * BB + gb) * HH + gj];

    const float* wbase = Ws + (mat * 16 + jq) * WP + ks * 4;

    for (int r = 0; r <= TT; r++) {
        const int cur = r & 1, nxt = cur ^ 1;

        // ---- stage h0[r-1], h1[r-2] tiles for this batch group ----
        for (int i = tid; i < 8 * 128; i += 384) {
            int b = i >> 7, kq = i & 127;
            *(float4*)&Hs0[b * HP + kq * 4] = *(const float4*)&g_h0[cur][bg * 8 + b][kq * 4];
            *(float4*)&Hs1[b * HP + kq * 4] = *(const float4*)&g_h1[cur][bg * 8 + b][kq * 4];
        }
        __syncthreads();

        // ---- compute: lane = 4j x 2b micro-tile over its k-slice -----------
        // k coverage: ks*4 + i*32 + {0..3}  (i = 0..15) -> full 512 across ks=0..7
        const float* hbase = ((mat == 2) ? Hs1 : Hs0) + (bq * 2) * HP + ks * 4;
        unsigned long long acc[4][2];
#pragma unroll
        for (int a = 0; a < 4; a++) { acc[a][0] = 0ull; acc[a][1] = 0ull; }

#pragma unroll
        for (int i = 0; i < 16; i++) {
            const float* wk = wbase + i * 32;
            const float* hk = hbase + i * 32;
            ulonglong2 hA = *(const ulonglong2*)hk;
            ulonglong2 hB = *(const ulonglong2*)(hk + HP);
#pragma unroll
            for (int jj = 0; jj < 4; jj++) {
                ulonglong2 w = *(const ulonglong2*)(wk + jj * 4 * WP);
                fma2(acc[jj][0], w.x, hA.x); fma2(acc[jj][0], w.y, hA.y);
                fma2(acc[jj][1], w.x, hB.x); fma2(acc[jj][1], w.y, hB.y);
            }
        }

        // ---- write partial sums ----
#pragma unroll
        for (int jj = 0; jj < 4; jj++)
#pragma unroll
            for (int bb = 0; bb < 2; bb++) {
                unsigned long long v = acc[jj][bb];
                float s = __uint_as_float((unsigned)v)
                        + __uint_as_float((unsigned)(v >> 32));
                red[((mat * 16 + jj * 4 + jq) * 8 + bq * 2 + bb) * RP + ks] = s;
            }
        __syncthreads();

        // ---- epilogue ----
        if (tid < 128) {
            if (r < TT) {
                float s = pv;
                const float* rb = red + ((size_t)ej * 8 + eb) * RP;
#pragma unroll
                for (int p = 0; p < 8; p++) s += rb[p];
                float hn = tanhf(s);
                g_h0[nxt][gb][gj] = hn;
                if (r == TT - 1)
                    out[(size_t)BB * TT * HH + (size_t)gb * HH + gj] = hn;
            }
        } else if (tid < 256) {
            if (r >= 1) {
                float s = b1s[ej];
                const float* rb1 = red + ((size_t)(16 + ej) * 8 + eb) * RP;
                const float* rb2 = red + ((size_t)(32 + ej) * 8 + eb) * RP;
#pragma unroll
                for (int p = 0; p < 8; p++) s += rb1[p] + rb2[p];
                float hn = tanhf(s);
                g_h1[nxt][gb][gj] = hn;
                const int t1 = r - 1;
                out[((size_t)gb * TT + t1) * HH + gj] = hn;
                if (t1 == TT - 1)
                    out[(size_t)BB * TT * HH + (size_t)BB * HH + (size_t)gb * HH + gj] = hn;
            }
        }

        // prefetch next round's pre value (independent of the barrier)
        if (tid < 128 && r + 1 < TT)
            pv = g_pre[((size_t)(r + 1) * BB + gb) * HH + gj];

        // ---- per-batch-group barrier (skip after final round) ----
        if (r < TT) {
            __syncthreads();
            if (tid == 0) {
                __threadfence();
                unsigned arrived = atomicAdd(cnt, 1u);
                if (arrived == (unsigned)(r * 32 + 31)) {
                    strel(gen, (unsigned)(r + 1));
                } else {
                    while (ldacq(gen) < (unsigned)(r + 1)) { }
                }
            }
            __syncthreads();
        }
    }
}

// ---------------- launch ----------------------------------------------------
extern "C" void kernel_launch(void* const* d_in, const int* in_sizes, int n_in,
                              void* d_out, int out_size)
{
    (void)in_sizes; (void)n_in; (void)out_size;
    const float* x    = (const float*)d_in[0];
    const float* wih0 = (const float*)d_in[1];
    const float* whh0 = (const float*)d_in[2];
    const float* bih0 = (const float*)d_in[3];
    const float* bhh0 = (const float*)d_in[4];
    const float* wih1 = (const float*)d_in[5];
    const float* whh1 = (const float*)d_in[6];
    const float* bih1 = (const float*)d_in[7];
    const float* bhh1 = (const float*)d_in[8];
    float* out = (float*)d_out;

    cudaFuncSetAttribute(rnn_fused,
                         cudaFuncAttributeMaxDynamicSharedMemorySize, SMEM_FUSED);

    init_state<<<128, 256>>>();

    dim3 gemmGrid(HH / 64, (TT * BB) / 64);   // (8, 512)
    gemm_pre<<<gemmGrid, 256>>>(x, wih0, bih0, bhh0);

    rnn_fused<<<128, 384, SMEM_FUSED>>>(whh0, wih1, whh1, bih1, bhh1, out);
}